// round 2
// baseline (speedup 1.0000x reference)
#include <cuda_runtime.h>
#include <math.h>

// ---------------------------------------------------------------------------
// ModalUncertaintyEstimator  (B=64, C=8, H=256, M=32)
//
// Pipeline:
//   k_stage1  : pruned DFT over y (folded cos/sin), per image -> g_T[img][x][64]
//   k_stage2  : pruned DFT over x (folded), -> modes; energies + per-(b,c) totals
//   k_mlp     : per-mode MLP (2->64->32->1, softplus) + errors/fractions/importance
//   k_pearson : per-mode spectra means + Pearson correlation over the 512 (b,c)
// ---------------------------------------------------------------------------

#define BC        512           // B*C
#define HH        256
#define MM        32
#define NIMG      1024          // pred images [0,512) then gt images [512,1024)
#define IMG_ELEMS 65536         // 256*256
#define MODES     1024          // 32*32
#define FEPS      1e-8f

// ---- output layout (concatenated reference tuple, all float32) ----
#define OFF_EN    0            // modal_energies        [512][1024]
#define OFF_UNC   524288       // modal_uncertainties   [512][1024]
#define OFF_FRAC  1048576      // energy_fractions      [512][1024]
#define OFF_WIMP  1572864      // weighted_importance   [512][1024]
#define OFF_USPEC 2097152      // uncertainty_spectrum  [1024]
#define OFF_ESPEC 2098176      // energy_spectrum       [1024]
#define OFF_ERR   2099200      // modal_errors          [512][1024]
#define OFF_CAL   2623488      // calibration_scores    [1024]

// ---- scratch (static device allocations; no cudaMalloc allowed) ----
__device__ float g_T[(size_t)NIMG * HH * 64];       // 64 MB: [img][x][0:32]=Tr, [32:64]=Ti
__device__ float g_mre[(size_t)NIMG * MODES];       // 4 MB
__device__ float g_mim[(size_t)NIMG * MODES];       // 4 MB
__device__ float g_total[BC];

// ===========================================================================
// Stage 1: per image, T[x][k2] = sum_y P[x][y] * exp(-2*pi*i*k2*y/256)
// Folding over y: Tr uses e=P[y]+P[256-y], Ti uses o=P[256-y]-P[y]  (y=1..127)
// plus endpoint terms P[0] and (-1)^k * P[128].
// ===========================================================================
#define TS   16      // tile rows per iteration
#define TPAD 260     // padded row stride (multiple of 4, bank-skewing)

__global__ __launch_bounds__(128) void k_stage1(const float* __restrict__ pred,
                                                const float* __restrict__ gt)
{
    __shared__ float cosW[127 * 32];     // cosW[(y-1)*32 + k], y = 1..127
    __shared__ float sinW[127 * 32];
    __shared__ float Pt[TS * TPAD];      // 16640 B ; total smem = 49152 B

    const int img = blockIdx.x;
    const float* src = (img < BC) ? (pred + (size_t)img * IMG_ELEMS)
                                  : (gt   + (size_t)(img - BC) * IMG_ELEMS);
    const int tid = threadIdx.x;

    // build folded twiddle tables: cos/sin(2*pi*y*k/256)
    for (int i = tid; i < 127 * 32; i += 128) {
        int y = (i >> 5) + 1;
        int k = i & 31;
        float a = (float)((y * k) & 255) * (1.0f / 128.0f);   // theta / pi
        cosW[i] = cospif(a);
        sinW[i] = sinpif(a);
    }
    __syncthreads();

    const int xi = tid >> 3;          // 0..15  (row within tile)
    const int kg = tid & 7;           // k base = kg*4
    float* Trow = g_T + (size_t)img * HH * 64;

    for (int x0 = 0; x0 < HH; x0 += TS) {
        __syncthreads();              // protect Pt from previous iteration's readers
        // coalesced float4 tile load: 16 rows x 256 cols
        {
            const float4* g4 = (const float4*)(src + (size_t)x0 * HH);
            for (int i = tid; i < TS * HH / 4; i += 128) {
                int row = i >> 6;              // (i*4)/256
                int col = (i & 63) * 4;
                *(float4*)&Pt[row * TPAD + col] = g4[i];
            }
        }
        __syncthreads();

        float4 tr = make_float4(0.f, 0.f, 0.f, 0.f);
        float4 ti = make_float4(0.f, 0.f, 0.f, 0.f);
        const float* prow = &Pt[xi * TPAD];

        #pragma unroll 4
        for (int y = 1; y <= 127; ++y) {
            float a = prow[y];
            float b = prow[256 - y];
            float e = a + b;          // cos (even) fold
            float o = b - a;          // Ti = sum o*sin
            float4 c = *(const float4*)&cosW[(y - 1) * 32 + kg * 4];
            float4 s = *(const float4*)&sinW[(y - 1) * 32 + kg * 4];
            tr.x += e * c.x; tr.y += e * c.y; tr.z += e * c.z; tr.w += e * c.w;
            ti.x += o * s.x; ti.y += o * s.y; ti.z += o * s.z; ti.w += o * s.w;
        }
        // endpoints: y=0 (cos=1) and y=128 (cos=(-1)^k, sin=0). k = 4*kg + j
        {
            float p0 = prow[0], p128 = prow[128];
            float ev = p0 + p128;     // k even
            float od = p0 - p128;     // k odd
            tr.x += ev; tr.y += od; tr.z += ev; tr.w += od;
        }

        float4* dst = (float4*)(Trow + (size_t)(x0 + xi) * 64);
        dst[kg]     = tr;     // Tr[k]
        dst[8 + kg] = ti;     // Ti[k]
    }
}

// ===========================================================================
// Stage 2: modes[k1][k2] = sum_x exp(-2*pi*i*k1*x/256) * T[x][k2]
// Folded over x (cos even, sin odd under x -> 256-x):
//   re = sum_{x=1..127} c*(tr[x]+tr[256-x]) + s*(ti[x]-ti[256-x])
//        + tr[0] + (-1)^k1 * tr[128]
//   im = sum_{x=1..127} c*(ti[x]+ti[256-x]) - s*(tr[x]-tr[256-x])
//        + ti[0] + (-1)^k1 * ti[128]
// One CTA per image; 4 warps = k1 groups of 8, lane = k2.
// ===========================================================================
__global__ __launch_bounds__(128) void k_stage2(float* __restrict__ out)
{
    __shared__ float costab[256];
    __shared__ float red[128];

    const int img = blockIdx.x;
    const int tid = threadIdx.x;

    for (int i = tid; i < 256; i += 128)
        costab[i] = cospif((float)i * (1.0f / 128.0f));
    __syncthreads();

    const int lane = tid & 31;           // k2
    const int k1b  = (tid >> 5) * 8;     // k1 base for this warp
    const float* T = g_T + (size_t)img * HH * 64;

    float re[8], im[8];
    #pragma unroll
    for (int i = 0; i < 8; ++i) { re[i] = 0.f; im[i] = 0.f; }

    for (int x = 1; x <= 127; ++x) {
        float tra = T[x * 64 + lane];
        float tia = T[x * 64 + 32 + lane];
        float trb = T[(256 - x) * 64 + lane];
        float tib = T[(256 - x) * 64 + 32 + lane];
        float Etr = tra + trb, Otr = tra - trb;
        float Eti = tia + tib, Oti = tia - tib;
        int m = (x * k1b) & 255;
        #pragma unroll
        for (int i = 0; i < 8; ++i) {
            float c = costab[m];
            float s = costab[(m + 192) & 255];     // sin(theta) = cos(theta - pi/2)
            re[i] += c * Etr + s * Oti;
            im[i] += c * Eti - s * Otr;
            m = (m + x) & 255;
        }
    }
    // endpoints x=0 and x=128
    {
        float tr0   = T[lane],             ti0   = T[32 + lane];
        float tr128 = T[128 * 64 + lane],  ti128 = T[128 * 64 + 32 + lane];
        #pragma unroll
        for (int i = 0; i < 8; ++i) {
            float sgn = ((k1b + i) & 1) ? -1.0f : 1.0f;
            re[i] += tr0 + sgn * tr128;
            im[i] += ti0 + sgn * ti128;
        }
    }

    const size_t mbase = (size_t)img * MODES;
    float esum = 0.f;
    #pragma unroll
    for (int i = 0; i < 8; ++i) {
        int idx = (k1b + i) * 32 + lane;
        g_mre[mbase + idx] = re[i];
        g_mim[mbase + idx] = im[i];
        if (img < BC) {
            float en = re[i] * re[i] + im[i] * im[i];
            out[OFF_EN + (size_t)img * MODES + idx] = en;
            esum += en;
        }
    }

    if (img < BC) {
        red[tid] = esum;
        __syncthreads();
        for (int s = 64; s > 0; s >>= 1) {
            if (tid < s) red[tid] += red[tid + s];
            __syncthreads();
        }
        if (tid == 0) g_total[img] = red[0];
    }
}

// ===========================================================================
// MLP per mode + element-wise outputs.
//   h1 = relu([re,im] @ W1 + b1)   (64)
//   h2 = relu(h1 @ W2 + b2)        (32)
//   u  = softplus(h2 @ W3 + b3)
// ===========================================================================
__global__ __launch_bounds__(256) void k_mlp(
    const float* __restrict__ W1, const float* __restrict__ b1,
    const float* __restrict__ W2, const float* __restrict__ b2,
    const float* __restrict__ W3, const float* __restrict__ b3,
    float* __restrict__ out)
{
    __shared__ float sW1[128];    // W1[2][64] row-major
    __shared__ float sb1[64];
    __shared__ float sW2[2048];   // W2[64][32] row-major
    __shared__ float sb2[32];
    __shared__ float sW3[32];
    __shared__ float sb3;

    const int tid = threadIdx.x;
    for (int i = tid; i < 128;  i += 256) sW1[i] = W1[i];
    for (int i = tid; i < 2048; i += 256) sW2[i] = W2[i];
    if (tid < 64) sb1[tid] = b1[tid];
    if (tid < 32) { sb2[tid] = b2[tid]; sW3[tid] = W3[tid]; }
    if (tid == 0) sb3 = b3[0];
    __syncthreads();

    const size_t g = (size_t)blockIdx.x * 256 + tid;   // 0..524287 (= bc*1024 + mode)
    const int bc = (int)(g >> 10);

    float xr = g_mre[g];
    float xv = g_mim[g];
    float gr = g_mre[(size_t)BC * MODES + g];
    float gi = g_mim[(size_t)BC * MODES + g];

    float acc[32];
    #pragma unroll
    for (int j = 0; j < 32; ++j) acc[j] = sb2[j];

    #pragma unroll 4
    for (int i = 0; i < 64; ++i) {
        float h = fmaf(xr, sW1[i], fmaf(xv, sW1[64 + i], sb1[i]));
        h = fmaxf(h, 0.f);
        const float* w2 = &sW2[i * 32];
        #pragma unroll
        for (int j = 0; j < 32; ++j) acc[j] = fmaf(h, w2[j], acc[j]);
    }

    float z = sb3;
    #pragma unroll
    for (int j = 0; j < 32; ++j) z = fmaf(fmaxf(acc[j], 0.f), sW3[j], z);

    // softplus(z) = max(z,0) + log1p(exp(-|z|))   (matches jax.nn.softplus)
    float u = fmaxf(z, 0.f) + log1pf(expf(-fabsf(z)));

    float en   = xr * xr + xv * xv;
    float frac = en / (g_total[bc] + FEPS);
    float dr = xr - gr, di = xv - gi;
    float err = dr * dr + di * di;

    out[OFF_UNC  + g] = u;
    out[OFF_FRAC + g] = frac;
    out[OFF_WIMP + g] = frac * u;
    out[OFF_ERR  + g] = err;
}

// ===========================================================================
// Per-mode reductions over the 512 (b,c) samples:
//   uncertainty_spectrum, energy_spectrum, Pearson(u, err)
// Two-pass centered computation (matches reference numerics).
// ===========================================================================
__global__ __launch_bounds__(128) void k_pearson(float* __restrict__ out)
{
    __shared__ float su[512], se[512];
    __shared__ float r1[128], r2[128], r3[128];

    const int mode = blockIdx.x;
    const int tid  = threadIdx.x;

    const float* unc = out + OFF_UNC;
    const float* err = out + OFF_ERR;
    const float* eng = out + OFF_EN;

    float lu = 0.f, le = 0.f, len = 0.f;
    #pragma unroll
    for (int r = 0; r < 4; ++r) {
        int bc = tid + r * 128;
        float u = unc[(size_t)bc * MODES + mode];
        float e = err[(size_t)bc * MODES + mode];
        float n = eng[(size_t)bc * MODES + mode];
        su[bc] = u; se[bc] = e;
        lu += u; le += e; len += n;
    }
    r1[tid] = lu; r2[tid] = le; r3[tid] = len;
    __syncthreads();
    for (int s = 64; s > 0; s >>= 1) {
        if (tid < s) { r1[tid] += r1[tid + s]; r2[tid] += r2[tid + s]; r3[tid] += r3[tid + s]; }
        __syncthreads();
    }
    const float SU = r1[0], SE = r2[0], SEN = r3[0];
    const float mu = SU * (1.0f / 512.0f);
    const float me = SE * (1.0f / 512.0f);
    __syncthreads();   // done reading r* before reuse

    float s1 = 0.f, s2 = 0.f, s3 = 0.f;
    #pragma unroll
    for (int r = 0; r < 4; ++r) {
        int bc = tid + r * 128;
        float uc = su[bc] - mu;
        float ec = se[bc] - me;
        s1 += uc * ec; s2 += uc * uc; s3 += ec * ec;
    }
    r1[tid] = s1; r2[tid] = s2; r3[tid] = s3;
    __syncthreads();
    for (int s = 64; s > 0; s >>= 1) {
        if (tid < s) { r1[tid] += r1[tid + s]; r2[tid] += r2[tid + s]; r3[tid] += r3[tid + s]; }
        __syncthreads();
    }

    if (tid == 0) {
        out[OFF_USPEC + mode] = SU  * (1.0f / 512.0f);
        out[OFF_ESPEC + mode] = SEN * (1.0f / 512.0f);
        float den = sqrtf(r2[0] * r3[0]);
        out[OFF_CAL + mode] = r1[0] / (den + FEPS);
    }
}

// ===========================================================================
extern "C" void kernel_launch(void* const* d_in, const int* in_sizes, int n_in,
                              void* d_out, int out_size)
{
    (void)in_sizes; (void)n_in; (void)out_size;
    const float* pred = (const float*)d_in[0];
    // d_in[1] ('uncertainty') is unused by the reference computation.
    const float* gt   = (const float*)d_in[2];
    const float* W1   = (const float*)d_in[3];
    const float* b1   = (const float*)d_in[4];
    const float* W2   = (const float*)d_in[5];
    const float* b2   = (const float*)d_in[6];
    const float* W3   = (const float*)d_in[7];
    const float* b3   = (const float*)d_in[8];
    float* out = (float*)d_out;

    k_stage1 <<<NIMG, 128>>>(pred, gt);
    k_stage2 <<<NIMG, 128>>>(out);
    k_mlp    <<<2048, 256>>>(W1, b1, W2, b2, W3, b3, out);
    k_pearson<<<MODES, 128>>>(out);
}